// round 1
// baseline (speedup 1.0000x reference)
#include <cuda_runtime.h>

#define RES 4096
#define NTOT (RES * RES)
#define HALF 5               // (WIDTH-1)/2, WIDTH=11
#define INV_AREA (1.0f / 121.0f)

// Scratch (device globals — no allocation allowed)
__device__ float g_V0[NTOT];
__device__ float g_V1[NTOT];
__device__ float g_E[NTOT];   // encoded: interior -> Cc (>0), boundary -> -bc-1 (<0)
__device__ float g_T[NTOT];   // objects_bounds, then reused as hbox partial

// ---------------------------------------------------------------------------
// Kernel 1: init V0, C_pos output, and objects_bounds
// ---------------------------------------------------------------------------
__global__ void k_init(const float* __restrict__ x,
                       const float* __restrict__ bt,
                       const float* __restrict__ bc,
                       const float* __restrict__ C,
                       float* __restrict__ cpos_out) {
    int i = blockIdx.x * blockDim.x + threadIdx.x;
    if (i >= NTOT) return;
    float btv = bt[i];
    float bcv = bc[i];
    float cp  = fmaxf(C[i], 0.0f);
    cpos_out[i] = cp;                       // C_pos output (second half of d_out)
    g_V0[i] = (btv > 0.0f) ? bcv : x[i];    // V0
    // objects_bounds = bc * (bt == 1) * (bc > 0)
    g_T[i] = (btv == 1.0f && bcv > 0.0f) ? bcv : 0.0f;
}

// ---------------------------------------------------------------------------
// Kernel 2: horizontal 11-wide box SUM (zero pad), g_T -> g_V1 (temp reuse)
// ---------------------------------------------------------------------------
__global__ void k_hbox() {
    int col = blockIdx.x * blockDim.x + threadIdx.x;
    int row = blockIdx.y;
    if (col >= RES) return;
    const float* src = g_T + (size_t)row * RES;
    float s = 0.0f;
    #pragma unroll
    for (int d = -HALF; d <= HALF; d++) {
        int c = col + d;
        if (c >= 0 && c < RES) s += __ldg(src + c);
    }
    g_V1[(size_t)row * RES + col] = s;
}

// ---------------------------------------------------------------------------
// Kernel 3: vertical 11-wide box SUM (zero pad) + build encoded E field
//   interior (bt==0): E = C_pos + extra   (>= 0.01 > 0)
//   boundary (bt>0):  E = -bc - 1          (in (-2,-1])
// ---------------------------------------------------------------------------
__global__ void k_vbox_combine(const float* __restrict__ bt,
                               const float* __restrict__ bc,
                               const float* __restrict__ cpos) {
    int col = blockIdx.x * blockDim.x + threadIdx.x;
    int row = blockIdx.y;
    if (col >= RES) return;
    size_t i = (size_t)row * RES + col;
    float btv = bt[i];
    if (btv == 0.0f) {
        float s = 0.0f;
        #pragma unroll
        for (int d = -HALF; d <= HALF; d++) {
            int r = row + d;
            if (r >= 0 && r < RES) s += __ldg(g_V1 + (size_t)r * RES + col);
        }
        g_E[i] = cpos[i] + s * INV_AREA;
    } else {
        g_E[i] = -bc[i] - 1.0f;
    }
}

// ---------------------------------------------------------------------------
// Kernel 4: one Jacobi sweep.
//   interior: Vn = 0.25*(up+down+left+right, edge-replicate) + Cc
//   boundary: Vn = bc  (decoded from E)
// ---------------------------------------------------------------------------
__global__ void k_jacobi(const float* __restrict__ Vin,
                         float* __restrict__ Vout) {
    int col = blockIdx.x * blockDim.x + threadIdx.x;
    int row = blockIdx.y * blockDim.y + threadIdx.y;
    if (col >= RES || row >= RES) return;
    size_t i = (size_t)row * RES + col;
    float e = g_E[i];
    if (e >= 0.0f) {
        int rm = (row > 0)       ? row - 1 : 0;
        int rp = (row < RES - 1) ? row + 1 : RES - 1;
        int cm = (col > 0)       ? col - 1 : 0;
        int cp = (col < RES - 1) ? col + 1 : RES - 1;
        float up    = __ldg(Vin + (size_t)rm * RES + col);
        float down  = __ldg(Vin + (size_t)rp * RES + col);
        float left  = __ldg(Vin + (size_t)row * RES + cm);
        float right = __ldg(Vin + (size_t)row * RES + cp);
        Vout[i] = 0.25f * (up + down + left + right) + e;
    } else {
        Vout[i] = -e - 1.0f;   // bc
    }
}

// ---------------------------------------------------------------------------
// Kernel 5: finalize: clamp >= MAX_VAL to 0.95, boundary -> bc
// ---------------------------------------------------------------------------
__global__ void k_final(const float* __restrict__ V,
                        float* __restrict__ out) {
    int i = blockIdx.x * blockDim.x + threadIdx.x;
    if (i >= NTOT) return;
    float e = g_E[i];
    float v = V[i];
    float r = (v >= 1.0f) ? 0.95f : v;
    if (e < 0.0f) r = -e - 1.0f;   // obj cells -> bc
    out[i] = r;
}

// ---------------------------------------------------------------------------
extern "C" void kernel_launch(void* const* d_in, const int* in_sizes, int n_in,
                              void* d_out, int out_size) {
    const float* x  = (const float*)d_in[0];
    const float* bt = (const float*)d_in[1];
    const float* bc = (const float*)d_in[2];
    const float* C  = (const float*)d_in[3];
    float* out  = (float*)d_out;          // first RES*RES = out
    float* cpos = out + (size_t)NTOT;     // second RES*RES = C_pos

    // init
    {
        dim3 b(256), g((NTOT + 255) / 256);
        k_init<<<g, b>>>(x, bt, bc, C, cpos);
    }
    // separable 11x11 box filter (sum, zero-pad)
    {
        dim3 b(256, 1), g(RES / 256, RES);
        k_hbox<<<g, b>>>();
        k_vbox_combine<<<g, b>>>(bt, bc, cpos);
    }
    // 20 Jacobi sweeps, ping-pong g_V0 <-> g_V1
    {
        dim3 b(128, 2), g(RES / 128, RES / 2);
        float *dv0, *dv1;
        cudaGetSymbolAddress((void**)&dv0, g_V0);
        cudaGetSymbolAddress((void**)&dv1, g_V1);
        for (int it = 0; it < 20; it++) {
            const float* src = (it & 1) ? dv1 : dv0;
            float*       dst = (it & 1) ? dv0 : dv1;
            k_jacobi<<<g, b>>>(src, dst);
        }
    }
    // finalize (after 20 iters result is in g_V0)
    {
        dim3 b(256), g((NTOT + 255) / 256);
        float* dv0;
        cudaGetSymbolAddress((void**)&dv0, g_V0);
        k_final<<<g, b>>>(dv0, out);
    }
}

// round 2
// speedup vs baseline: 2.5095x; 2.5095x over previous
#include <cuda_runtime.h>

#define RES 4096
#define NQ  (RES / 4)        // float4 per row = 1024
#define NTOT (RES * RES)
#define HALF 5               // (WIDTH-1)/2, WIDTH=11
#define INV_AREA (1.0f / 121.0f)

// Scratch (device globals — no allocation allowed)
__device__ float g_V0[NTOT];
__device__ float g_V1[NTOT];
__device__ float g_E[NTOT];   // encoded: interior -> Cc (>0), boundary -> -bc-1 (<0)
__device__ float g_T[NTOT];   // objects_bounds, then hbox partial sums

// ---------------------------------------------------------------------------
// Kernel 1: init V0, C_pos output, objects_bounds   (float4)
// ---------------------------------------------------------------------------
__global__ void k_init(const float4* __restrict__ x,
                       const float4* __restrict__ bt,
                       const float4* __restrict__ bc,
                       const float4* __restrict__ C,
                       float4* __restrict__ cpos_out) {
    int i = blockIdx.x * blockDim.x + threadIdx.x;
    if (i >= NTOT / 4) return;
    float4 btv = bt[i];
    float4 bcv = bc[i];
    float4 cv  = C[i];
    float4 xv  = x[i];
    float4 cp;
    cp.x = fmaxf(cv.x, 0.f); cp.y = fmaxf(cv.y, 0.f);
    cp.z = fmaxf(cv.z, 0.f); cp.w = fmaxf(cv.w, 0.f);
    cpos_out[i] = cp;
    float4 v0;
    v0.x = (btv.x > 0.f) ? bcv.x : xv.x;
    v0.y = (btv.y > 0.f) ? bcv.y : xv.y;
    v0.z = (btv.z > 0.f) ? bcv.z : xv.z;
    v0.w = (btv.w > 0.f) ? bcv.w : xv.w;
    ((float4*)g_V0)[i] = v0;
    float4 t;
    t.x = (btv.x == 1.f && bcv.x > 0.f) ? bcv.x : 0.f;
    t.y = (btv.y == 1.f && bcv.y > 0.f) ? bcv.y : 0.f;
    t.z = (btv.z == 1.f && bcv.z > 0.f) ? bcv.z : 0.f;
    t.w = (btv.w == 1.f && bcv.w > 0.f) ? bcv.w : 0.f;
    ((float4*)g_T)[i] = t;
}

// ---------------------------------------------------------------------------
// Kernel 2: horizontal 11-wide box SUM (zero pad), g_T -> g_V1
// Each thread produces 4 outputs (one float4) via sliding sums.
// ---------------------------------------------------------------------------
__global__ void k_hbox() {
    int c4  = blockIdx.x * blockDim.x + threadIdx.x;   // 0..NQ-1
    int row = blockIdx.y;
    if (c4 >= NQ) return;
    int c0 = c4 * 4;
    const float* src = g_T + (size_t)row * RES;
    float v[14];
    #pragma unroll
    for (int d = 0; d < 14; d++) {
        int c = c0 - HALF + d;
        v[d] = (c >= 0 && c < RES) ? __ldg(src + c) : 0.f;
    }
    float s = 0.f;
    #pragma unroll
    for (int d = 0; d < 11; d++) s += v[d];
    float4 o;
    o.x = s;
    s += v[11] - v[0];  o.y = s;
    s += v[12] - v[1];  o.z = s;
    s += v[13] - v[2];  o.w = s;
    ((float4*)g_V1)[(size_t)row * NQ + c4] = o;
}

// ---------------------------------------------------------------------------
// Kernel 3: vertical 11-wide box SUM (zero pad) + build encoded E   (float4)
// ---------------------------------------------------------------------------
__global__ void k_vbox_combine(const float4* __restrict__ bt,
                               const float4* __restrict__ bc,
                               const float4* __restrict__ cpos) {
    int c4  = blockIdx.x * blockDim.x + threadIdx.x;
    int row = blockIdx.y;
    if (c4 >= NQ) return;
    size_t i = (size_t)row * NQ + c4;
    float4 s = make_float4(0.f, 0.f, 0.f, 0.f);
    const float4* V1 = (const float4*)g_V1;
    #pragma unroll
    for (int d = -HALF; d <= HALF; d++) {
        int r = row + d;
        if (r >= 0 && r < RES) {
            float4 t = __ldg(V1 + (size_t)r * NQ + c4);
            s.x += t.x; s.y += t.y; s.z += t.z; s.w += t.w;
        }
    }
    float4 btv = bt[i];
    float4 bcv = bc[i];
    float4 cp  = cpos[i];
    float4 e;
    e.x = (btv.x == 0.f) ? cp.x + s.x * INV_AREA : -bcv.x - 1.f;
    e.y = (btv.y == 0.f) ? cp.y + s.y * INV_AREA : -bcv.y - 1.f;
    e.z = (btv.z == 0.f) ? cp.z + s.z * INV_AREA : -bcv.z - 1.f;
    e.w = (btv.w == 0.f) ? cp.w + s.w * INV_AREA : -bcv.w - 1.f;
    ((float4*)g_E)[i] = e;
}

// ---------------------------------------------------------------------------
// Kernel 4: one Jacobi sweep, float4 per thread.
// FINAL!=0 applies the output clamp (fused last pass).
// ---------------------------------------------------------------------------
template <int FINAL>
__global__ void k_jacobi(const float4* __restrict__ Vin,
                         float4* __restrict__ Vout) {
    int c4  = blockIdx.x * blockDim.x + threadIdx.x;   // 0..NQ-1
    int row = blockIdx.y;
    size_t i = (size_t)row * NQ + c4;
    int rm = (row > 0)       ? row - 1 : 0;
    int rp = (row < RES - 1) ? row + 1 : RES - 1;
    float4 e  = ((const float4*)g_E)[i];
    float4 up = __ldg(Vin + (size_t)rm * NQ + c4);
    float4 dn = __ldg(Vin + (size_t)rp * NQ + c4);
    float4 ce = __ldg(Vin + i);
    const float* Vf = (const float*)Vin;
    float lft = (c4 > 0)      ? __ldg(Vf + (size_t)row * RES + c4 * 4 - 1) : ce.x;
    float rgt = (c4 < NQ - 1) ? __ldg(Vf + (size_t)row * RES + c4 * 4 + 4) : ce.w;
    float4 o;
    o.x = (e.x >= 0.f) ? 0.25f * (up.x + dn.x + lft  + ce.y) + e.x : -e.x - 1.f;
    o.y = (e.y >= 0.f) ? 0.25f * (up.y + dn.y + ce.x + ce.z) + e.y : -e.y - 1.f;
    o.z = (e.z >= 0.f) ? 0.25f * (up.z + dn.z + ce.y + ce.w) + e.z : -e.z - 1.f;
    o.w = (e.w >= 0.f) ? 0.25f * (up.w + dn.w + ce.z + rgt ) + e.w : -e.w - 1.f;
    if (FINAL) {
        // out = where(V>=1, 0.95, V); boundary already = bc (<1, clamp no-op)
        o.x = (o.x >= 1.f) ? 0.95f : o.x;
        o.y = (o.y >= 1.f) ? 0.95f : o.y;
        o.z = (o.z >= 1.f) ? 0.95f : o.z;
        o.w = (o.w >= 1.f) ? 0.95f : o.w;
    }
    Vout[i] = o;
}

// ---------------------------------------------------------------------------
extern "C" void kernel_launch(void* const* d_in, const int* in_sizes, int n_in,
                              void* d_out, int out_size) {
    const float* x  = (const float*)d_in[0];
    const float* bt = (const float*)d_in[1];
    const float* bc = (const float*)d_in[2];
    const float* C  = (const float*)d_in[3];
    float* out  = (float*)d_out;          // first RES*RES = out
    float* cpos = out + (size_t)NTOT;     // second RES*RES = C_pos

    // init (float4)
    {
        dim3 b(256), g((NTOT / 4 + 255) / 256);
        k_init<<<g, b>>>((const float4*)x, (const float4*)bt,
                         (const float4*)bc, (const float4*)C,
                         (float4*)cpos);
    }
    // separable 11x11 box filter (sum, zero-pad)
    {
        dim3 b(256, 1), g(NQ / 256, RES);
        k_hbox<<<g, b>>>();
        k_vbox_combine<<<g, b>>>((const float4*)bt, (const float4*)bc,
                                 (const float4*)cpos);
    }
    // 20 Jacobi sweeps, ping-pong; last sweep writes clamped result to out
    {
        dim3 b(256, 1), g(NQ / 256, RES);
        float *dv0, *dv1;
        cudaGetSymbolAddress((void**)&dv0, g_V0);
        cudaGetSymbolAddress((void**)&dv1, g_V1);
        for (int it = 0; it < 19; it++) {
            const float* src = (it & 1) ? dv1 : dv0;
            float*       dst = (it & 1) ? dv0 : dv1;
            k_jacobi<0><<<g, b>>>((const float4*)src, (float4*)dst);
        }
        // iter 19 reads dv1 (19 is odd), writes clamped output
        k_jacobi<1><<<g, b>>>((const float4*)dv1, (float4*)out);
    }
}

// round 3
// speedup vs baseline: 3.8889x; 1.5497x over previous
#include <cuda_runtime.h>

#define RES 4096
#define NQ  (RES / 4)
#define NTOT (RES * RES)
#define HALF 5
#define INV_AREA (1.0f / 121.0f)

// Temporal-blocked Jacobi tile params
#define KF 4                 // fused steps per pass
#define RX 128               // region cols (32 float4)
#define RY 64                // region rows
#define TX 120               // valid output cols (RX - 2*KF)
#define TY 56                // valid output rows (RY - 2*KF)

// Scratch (device globals — no allocation allowed)
__device__ float g_V0[NTOT];
__device__ float g_V1[NTOT];
__device__ float g_E[NTOT];
__device__ float g_T[NTOT];

// ---------------------------------------------------------------------------
// Kernel 1: init V0, C_pos output, objects_bounds   (float4)
// ---------------------------------------------------------------------------
__global__ void k_init(const float4* __restrict__ x,
                       const float4* __restrict__ bt,
                       const float4* __restrict__ bc,
                       const float4* __restrict__ C,
                       float4* __restrict__ cpos_out) {
    int i = blockIdx.x * blockDim.x + threadIdx.x;
    if (i >= NTOT / 4) return;
    float4 btv = bt[i];
    float4 bcv = bc[i];
    float4 cv  = C[i];
    float4 xv  = x[i];
    float4 cp;
    cp.x = fmaxf(cv.x, 0.f); cp.y = fmaxf(cv.y, 0.f);
    cp.z = fmaxf(cv.z, 0.f); cp.w = fmaxf(cv.w, 0.f);
    cpos_out[i] = cp;
    float4 v0;
    v0.x = (btv.x > 0.f) ? bcv.x : xv.x;
    v0.y = (btv.y > 0.f) ? bcv.y : xv.y;
    v0.z = (btv.z > 0.f) ? bcv.z : xv.z;
    v0.w = (btv.w > 0.f) ? bcv.w : xv.w;
    ((float4*)g_V0)[i] = v0;
    float4 t;
    t.x = (btv.x == 1.f && bcv.x > 0.f) ? bcv.x : 0.f;
    t.y = (btv.y == 1.f && bcv.y > 0.f) ? bcv.y : 0.f;
    t.z = (btv.z == 1.f && bcv.z > 0.f) ? bcv.z : 0.f;
    t.w = (btv.w == 1.f && bcv.w > 0.f) ? bcv.w : 0.f;
    ((float4*)g_T)[i] = t;
}

// ---------------------------------------------------------------------------
// Kernel 2: horizontal 11-wide box SUM (zero pad), g_T -> g_V1
// ---------------------------------------------------------------------------
__global__ void k_hbox() {
    int c4  = blockIdx.x * blockDim.x + threadIdx.x;
    int row = blockIdx.y;
    if (c4 >= NQ) return;
    int c0 = c4 * 4;
    const float* src = g_T + (size_t)row * RES;
    float v[14];
    #pragma unroll
    for (int d = 0; d < 14; d++) {
        int c = c0 - HALF + d;
        v[d] = (c >= 0 && c < RES) ? __ldg(src + c) : 0.f;
    }
    float s = 0.f;
    #pragma unroll
    for (int d = 0; d < 11; d++) s += v[d];
    float4 o;
    o.x = s;
    s += v[11] - v[0];  o.y = s;
    s += v[12] - v[1];  o.z = s;
    s += v[13] - v[2];  o.w = s;
    ((float4*)g_V1)[(size_t)row * NQ + c4] = o;
}

// ---------------------------------------------------------------------------
// Kernel 3: vertical 11-wide box SUM (zero pad) + build encoded E   (float4)
// ---------------------------------------------------------------------------
__global__ void k_vbox_combine(const float4* __restrict__ bt,
                               const float4* __restrict__ bc,
                               const float4* __restrict__ cpos) {
    int c4  = blockIdx.x * blockDim.x + threadIdx.x;
    int row = blockIdx.y;
    if (c4 >= NQ) return;
    size_t i = (size_t)row * NQ + c4;
    float4 s = make_float4(0.f, 0.f, 0.f, 0.f);
    const float4* V1 = (const float4*)g_V1;
    #pragma unroll
    for (int d = -HALF; d <= HALF; d++) {
        int r = row + d;
        if (r >= 0 && r < RES) {
            float4 t = __ldg(V1 + (size_t)r * NQ + c4);
            s.x += t.x; s.y += t.y; s.z += t.z; s.w += t.w;
        }
    }
    float4 btv = bt[i];
    float4 bcv = bc[i];
    float4 cp  = cpos[i];
    float4 e;
    e.x = (btv.x == 0.f) ? cp.x + s.x * INV_AREA : -bcv.x - 1.f;
    e.y = (btv.y == 0.f) ? cp.y + s.y * INV_AREA : -bcv.y - 1.f;
    e.z = (btv.z == 0.f) ? cp.z + s.z * INV_AREA : -bcv.z - 1.f;
    e.w = (btv.w == 0.f) ? cp.w + s.w * INV_AREA : -bcv.w - 1.f;
    ((float4*)g_E)[i] = e;
}

// ---------------------------------------------------------------------------
// Kernel 4: KF fused Jacobi steps on a 128x64 smem tile.
// Thread layout: tx = lane (0..31, one float4 in x), ty = warp (0..7, 8 rows).
// E kept in registers; vertical rolling (prev/cur/nxt); horiz via shfl.
// ---------------------------------------------------------------------------
__device__ __forceinline__ float4 ld4s(const float* b, int r, int tx) {
    return *(const float4*)(b + r * RX + 4 * tx);
}
__device__ __forceinline__ void st4s(float* b, int r, int tx, float4 v) {
    *(float4*)(b + r * RX + 4 * tx) = v;
}

__global__ __launch_bounds__(256)
void k_jfuse(const float* __restrict__ Vin, float* __restrict__ Vout, int isfinal) {
    extern __shared__ float smem[];
    float* sA = smem;              // RY*RX
    float* sB = smem + RY * RX;

    int tx = threadIdx.x & 31;
    int ty = threadIdx.x >> 5;
    int gr0 = blockIdx.y * TY - KF;        // global row of region row 0 (may be <0)
    int gc0 = blockIdx.x * TX - KF;        // global col of region col 0 (may be <0)
    int cb  = gc0 + tx * 4;                // global col of this thread's float4
    int r0  = ty * 8;

    bool colfast = (cb >= 0) && (cb + 3 < RES);
    bool is_ledge = (cb == 0);             // .x sits on global left edge
    bool is_redge = (cb + 3 == RES - 1);   // .w sits on global right edge

    // ---- fill: V -> sA, E -> registers ----
    float4 e[8];
    #pragma unroll
    for (int j = 0; j < 8; j++) {
        int r = r0 + j;
        int gr = min(max(gr0 + r, 0), RES - 1);
        size_t rowoff = (size_t)gr * RES;
        float4 v, ev;
        if (colfast) {
            v  = *(const float4*)(Vin + rowoff + cb);
            ev = *(const float4*)(g_E + rowoff + cb);
        } else {
            int c0i = min(max(cb + 0, 0), RES - 1);
            int c1i = min(max(cb + 1, 0), RES - 1);
            int c2i = min(max(cb + 2, 0), RES - 1);
            int c3i = min(max(cb + 3, 0), RES - 1);
            v  = make_float4(Vin[rowoff + c0i], Vin[rowoff + c1i],
                             Vin[rowoff + c2i], Vin[rowoff + c3i]);
            ev = make_float4(g_E[rowoff + c0i], g_E[rowoff + c1i],
                             g_E[rowoff + c2i], g_E[rowoff + c3i]);
        }
        st4s(sA, r, tx, v);
        e[j] = ev;
    }
    __syncthreads();

    const float* bin = sA;
    float* bout = sB;

    #pragma unroll
    for (int s = 0; s < KF; s++) {
        bool last = (s == KF - 1);
        float4 cur  = ld4s(bin, r0, tx);
        float4 prev = ld4s(bin, (r0 > 0) ? r0 - 1 : 0, tx);
        #pragma unroll
        for (int j = 0; j < 8; j++) {
            int r = r0 + j;
            float4 nxt = ld4s(bin, (r < RY - 1) ? r + 1 : r, tx);
            int grr = gr0 + r;
            bool top = (grr <= 0);
            bool bot = (grr >= RES - 1);
            float4 up = top ? cur : prev;
            float4 dn = bot ? cur : nxt;
            float lf = __shfl_up_sync(0xffffffffu, cur.w, 1);
            float rg = __shfl_down_sync(0xffffffffu, cur.x, 1);
            if (tx == 0 || is_ledge)  lf = cur.x;
            if (tx == 31 || is_redge) rg = cur.w;
            float4 ee = e[j];
            float4 o;
            o.x = (ee.x >= 0.f) ? 0.25f * (up.x + dn.x + lf    + cur.y) + ee.x : -ee.x - 1.f;
            o.y = (ee.y >= 0.f) ? 0.25f * (up.y + dn.y + cur.x + cur.z) + ee.y : -ee.y - 1.f;
            o.z = (ee.z >= 0.f) ? 0.25f * (up.z + dn.z + cur.y + cur.w) + ee.z : -ee.z - 1.f;
            o.w = (ee.w >= 0.f) ? 0.25f * (up.w + dn.w + cur.z + rg   ) + ee.w : -ee.w - 1.f;
            if (!last) {
                st4s(bout, r, tx, o);
            } else {
                // write valid region straight to gmem
                if (r >= KF && r < RY - KF && tx >= 1 && tx <= 30) {
                    int gr = gr0 + r;
                    if (gr < RES && cb + 3 < RES) {
                        if (isfinal) {
                            o.x = (o.x >= 1.f) ? 0.95f : o.x;
                            o.y = (o.y >= 1.f) ? 0.95f : o.y;
                            o.z = (o.z >= 1.f) ? 0.95f : o.z;
                            o.w = (o.w >= 1.f) ? 0.95f : o.w;
                        }
                        *(float4*)(Vout + (size_t)gr * RES + cb) = o;
                    }
                }
            }
            prev = cur; cur = nxt;
        }
        if (!last) {
            __syncthreads();
            const float* t = bin; bin = bout; bout = (float*)t;
        }
    }
}

// ---------------------------------------------------------------------------
extern "C" void kernel_launch(void* const* d_in, const int* in_sizes, int n_in,
                              void* d_out, int out_size) {
    const float* x  = (const float*)d_in[0];
    const float* bt = (const float*)d_in[1];
    const float* bc = (const float*)d_in[2];
    const float* C  = (const float*)d_in[3];
    float* out  = (float*)d_out;
    float* cpos = out + (size_t)NTOT;

    // init (float4)
    {
        dim3 b(256), g((NTOT / 4 + 255) / 256);
        k_init<<<g, b>>>((const float4*)x, (const float4*)bt,
                         (const float4*)bc, (const float4*)C,
                         (float4*)cpos);
    }
    // separable 11x11 box filter
    {
        dim3 b(256, 1), g(NQ / 256, RES);
        k_hbox<<<g, b>>>();
        k_vbox_combine<<<g, b>>>((const float4*)bt, (const float4*)bc,
                                 (const float4*)cpos);
    }
    // 20 Jacobi iters = 5 fused passes of KF=4
    {
        static int smem_set = 0;
        int smem_bytes = 2 * RY * RX * (int)sizeof(float);   // 64 KB
        if (!smem_set) {
            cudaFuncSetAttribute(k_jfuse,
                cudaFuncAttributeMaxDynamicSharedMemorySize, smem_bytes);
            smem_set = 1;
        }
        float *dv0, *dv1;
        cudaGetSymbolAddress((void**)&dv0, g_V0);
        cudaGetSymbolAddress((void**)&dv1, g_V1);
        dim3 b(256), g((RES + TX - 1) / TX, (RES + TY - 1) / TY);   // 35 x 74
        k_jfuse<<<g, b, smem_bytes>>>(dv0, dv1, 0);
        k_jfuse<<<g, b, smem_bytes>>>(dv1, dv0, 0);
        k_jfuse<<<g, b, smem_bytes>>>(dv0, dv1, 0);
        k_jfuse<<<g, b, smem_bytes>>>(dv1, dv0, 0);
        k_jfuse<<<g, b, smem_bytes>>>(dv0, out, 1);   // final 4 steps + clamp
    }
}